// round 5
// baseline (speedup 1.0000x reference)
#include <cuda_runtime.h>
#include <math.h>

// ---------------------------------------------------------------------------
// GATv2 x3 encoder.  N=100000 nodes, E=1600000 edges.
// CSR-by-dst + fused unnormalized-softmax aggregation.
// gat_node: We in registers, uniform-ldg edge features, f32x2 ef math.
// ---------------------------------------------------------------------------

constexpr int NMAX = 100000;
constexpr int EMAX = 1600000;

__device__ float g_xl[(size_t)NMAX * 128];
__device__ float g_xr[(size_t)NMAX * 128];
__device__ float g_h[(size_t)NMAX * 64];
__device__ int   g_cnt[NMAX];
__device__ int   g_cur[NMAX];
__device__ int   g_rowptr[NMAX + 1];
__device__ int   g_eids[EMAX];
__device__ int   g_srcs[EMAX];
__device__ float g_eas[(size_t)EMAX * 10];

// ---- f32x2 packed helpers -------------------------------------------------
__device__ __forceinline__ unsigned long long pk2(float lo, float hi) {
    unsigned long long r;
    asm("mov.b64 %0, {%1, %2};" : "=l"(r)
        : "r"(__float_as_uint(lo)), "r"(__float_as_uint(hi)));
    return r;
}
__device__ __forceinline__ unsigned long long splat2(float v) {
    unsigned long long r;
    asm("mov.b64 %0, {%1, %1};" : "=l"(r) : "r"(__float_as_uint(v)));
    return r;
}
__device__ __forceinline__ void upk2(float& lo, float& hi, unsigned long long v) {
    unsigned int a, b;
    asm("mov.b64 {%0, %1}, %2;" : "=r"(a), "=r"(b) : "l"(v));
    lo = __uint_as_float(a); hi = __uint_as_float(b);
}
__device__ __forceinline__ void fma2(unsigned long long& d,
                                     unsigned long long a, unsigned long long b) {
    asm("fma.rn.f32x2 %0, %1, %2, %0;" : "+l"(d) : "l"(a), "l"(b));
}

// ---------------------------------------------------------------------------
// Node transform: xl = act(in) @ Wl + bl ; xr = act(in) @ Wr + br
// ---------------------------------------------------------------------------
template <int FIN, int HC, bool ACT, int NPW>
__global__ __launch_bounds__(256) void node_gemm(
    const float* __restrict__ in,
    const float* __restrict__ Wl, const float* __restrict__ bl,
    const float* __restrict__ Wr, const float* __restrict__ br,
    float* __restrict__ xl, float* __restrict__ xr, int n)
{
    extern __shared__ float sW[];  // [FIN][2*HC]
    constexpr int OC  = 2 * HC;
    constexpr int CPL = OC / 32;   // cols per lane (4 or 8)
    constexpr int CP2 = CPL / 2;   // f32x2 pairs per lane
    constexpr int R   = (FIN + 31) / 32;

    for (int i = threadIdx.x; i < FIN * HC; i += blockDim.x) {
        int k = i / HC, c = i % HC;
        sW[k * OC + c]      = Wl[i];
        sW[k * OC + HC + c] = Wr[i];
    }
    __syncthreads();

    const int lane = threadIdx.x & 31;
    const int warp = (blockIdx.x * blockDim.x + threadIdx.x) >> 5;
    const int nw   = (gridDim.x * blockDim.x) >> 5;

    const int  c0  = lane * CPL;
    const bool isL = c0 < HC;
    const int  cc  = isL ? c0 : c0 - HC;
    const float* bb = isL ? bl : br;
    float bias[CPL];
#pragma unroll
    for (int j = 0; j < CPL; j++) bias[j] = bb[cc + j];
    float* const obase = (isL ? xl : xr) + cc;

    for (int n0 = warp * NPW; n0 < n; n0 += nw * NPW) {
        float xreg[NPW][R];
#pragma unroll
        for (int p = 0; p < NPW; p++) {
            const bool ok = (n0 + p) < n;
#pragma unroll
            for (int r = 0; r < R; r++) {
                int k = r * 32 + lane;
                float v = (ok && k < FIN) ? in[(size_t)(n0 + p) * FIN + k] : 0.f;
                if (ACT) v = v > 0.f ? v : 0.01f * v;
                xreg[p][r] = v;
            }
        }

        unsigned long long a[NPW][CP2];
#pragma unroll
        for (int p = 0; p < NPW; p++)
#pragma unroll
            for (int j = 0; j < CP2; j++) a[p][j] = 0ull;

#pragma unroll
        for (int r = 0; r < R; r++) {
            const int kmax = (FIN - r * 32) < 32 ? (FIN - r * 32) : 32;
#pragma unroll 4
            for (int k2 = 0; k2 < kmax; k2++) {
                const int k = r * 32 + k2;
                unsigned long long w[CP2];
                const ulonglong2* wp =
                    reinterpret_cast<const ulonglong2*>(sW + k * OC + c0);
                {
                    ulonglong2 t = wp[0];
                    w[0] = t.x; w[1] = t.y;
                }
                if constexpr (CP2 == 4) {
                    ulonglong2 t = wp[1];
                    w[2] = t.x; w[3] = t.y;
                }
#pragma unroll
                for (int p = 0; p < NPW; p++) {
                    float v = __shfl_sync(0xffffffffu, xreg[p][r], k2);
                    unsigned long long vv = splat2(v);
#pragma unroll
                    for (int j = 0; j < CP2; j++) fma2(a[p][j], vv, w[j]);
                }
            }
        }

#pragma unroll
        for (int p = 0; p < NPW; p++) {
            if ((n0 + p) >= n) break;
            float o[CPL];
#pragma unroll
            for (int j = 0; j < CP2; j++) upk2(o[2 * j], o[2 * j + 1], a[p][j]);
#pragma unroll
            for (int j = 0; j < CPL; j++) o[j] += bias[j];
            float* op = obase + (size_t)(n0 + p) * HC;
            reinterpret_cast<float4*>(op)[0] =
                make_float4(o[0], o[1], o[2], o[3]);
            if constexpr (CPL == 8) {
                reinterpret_cast<float4*>(op)[1] =
                    make_float4(o[4], o[5], o[6], o[7]);
            }
        }
    }
}

// ---------------------------------------------------------------------------
// CSR build
// ---------------------------------------------------------------------------
__global__ __launch_bounds__(256) void zero_cnt(int* __restrict__ cnt, int n) {
    int t = blockIdx.x * blockDim.x + threadIdx.x;
    if (t < n) cnt[t] = 0;
}

__global__ __launch_bounds__(256) void hist_kernel(
    const int* __restrict__ dst, int* __restrict__ cnt, int E)
{
    int e = blockIdx.x * blockDim.x + threadIdx.x;
    if (e < E) atomicAdd(&cnt[dst[e]], 1);
}

__global__ __launch_bounds__(1024) void scan_kernel(
    const int* __restrict__ cnt, int* __restrict__ rowptr,
    int* __restrict__ cur, int n)
{
    __shared__ int ssum[1024];
    const int t = threadIdx.x;
    const int chunk = (n + 1023) / 1024;
    const int beg = t * chunk;
    const int end = min(beg + chunk, n);
    int s = 0;
    for (int i = beg; i < end; i++) s += cnt[i];
    ssum[t] = s;
    __syncthreads();
    for (int off = 1; off < 1024; off <<= 1) {
        int v = 0;
        if (t >= off) v = ssum[t - off];
        __syncthreads();
        if (t >= off) ssum[t] += v;
        __syncthreads();
    }
    int p = (t == 0) ? 0 : ssum[t - 1];
    for (int i = beg; i < end; i++) {
        rowptr[i] = p; cur[i] = p; p += cnt[i];
    }
    if (t == 1023) rowptr[n] = ssum[1023];
}

__global__ __launch_bounds__(256) void scatter_kernel(
    const int* __restrict__ src, const int* __restrict__ dst,
    int* __restrict__ cur, int* __restrict__ eids, int* __restrict__ srcs, int E)
{
    int e = blockIdx.x * blockDim.x + threadIdx.x;
    if (e >= E) return;
    int pos = atomicAdd(&cur[dst[e]], 1);
    eids[pos] = e;
    srcs[pos] = src[e];
}

__global__ __launch_bounds__(256) void permute_ea(
    const float* __restrict__ ea, const int* __restrict__ eids,
    float* __restrict__ eas, int total)  // total = E*10
{
    int j = blockIdx.x * blockDim.x + threadIdx.x;
    if (j >= total) return;
    int pos = j / 10, k = j - pos * 10;
    eas[j] = ea[(size_t)eids[pos] * 10 + k];
}

// ---------------------------------------------------------------------------
// Fused per-node GATv2: logits + unnormalized softmax + aggregation.
// One warp per destination node; edges unrolled by 2.
// We in registers; ea via uniform ldg broadcast; f32x2 ef math with xr folded
// into the accumulator init.
// ---------------------------------------------------------------------------
template <int HC, bool CONCAT>
__global__ __launch_bounds__(256) void gat_node(
    const float* __restrict__ xl, const float* __restrict__ xr,
    const float* __restrict__ eas, const int* __restrict__ srcs,
    const int* __restrict__ rowptr,
    const float* __restrict__ We, const float* __restrict__ att,
    const float* __restrict__ bias, float* __restrict__ out, int n)
{
    constexpr int V = HC / 32;  // 2 or 4 channels per lane
    constexpr int P = V / 2;    // f32x2 pairs per lane

    const int lane = threadIdx.x & 31;
    const int d = (blockIdx.x * blockDim.x + threadIdx.x) >> 5;
    if (d >= n) return;
    const int c0 = lane * V;

    // We columns for this lane, in registers (packed pairs)
    unsigned long long Wreg[10][P];
#pragma unroll
    for (int k = 0; k < 10; k++)
#pragma unroll
        for (int j = 0; j < P; j++)
            Wreg[k][j] = __ldg(reinterpret_cast<const unsigned long long*>(
                We + k * HC + c0 + 2 * j));

    float attv[V];
#pragma unroll
    for (int v = 0; v < V; v++) attv[v] = att[c0 + v];

    // xr folded into ef accumulator init
    unsigned long long efInit[P];
    if constexpr (V == 4) {
        float4 u = reinterpret_cast<const float4*>(xr + (size_t)d * HC)[lane];
        efInit[0] = pk2(u.x, u.y);
        efInit[1] = pk2(u.z, u.w);
    } else {
        float2 u = reinterpret_cast<const float2*>(xr + (size_t)d * HC)[lane];
        efInit[0] = pk2(u.x, u.y);
    }

    const int beg = rowptr[d], end = rowptr[d + 1];
    float s = 0.f;
    float acc[V];
#pragma unroll
    for (int v = 0; v < V; v++) acc[v] = 0.f;

    int i = beg;
    for (; i + 1 < end; i += 2) {
        const int sA = srcs[i], sB = srcs[i + 1];
        float xA[V], xB[V];
        if constexpr (V == 4) {
            float4 t = reinterpret_cast<const float4*>(xl + (size_t)sA * HC)[lane];
            xA[0] = t.x; xA[1] = t.y; xA[2] = t.z; xA[3] = t.w;
            float4 u = reinterpret_cast<const float4*>(xl + (size_t)sB * HC)[lane];
            xB[0] = u.x; xB[1] = u.y; xB[2] = u.z; xB[3] = u.w;
        } else {
            float2 t = reinterpret_cast<const float2*>(xl + (size_t)sA * HC)[lane];
            xA[0] = t.x; xA[1] = t.y;
            float2 u = reinterpret_cast<const float2*>(xl + (size_t)sB * HC)[lane];
            xB[0] = u.x; xB[1] = u.y;
        }
        // uniform loads of edge features (all lanes same address -> broadcast)
        const float2* eA = reinterpret_cast<const float2*>(eas + (size_t)i * 10);
        const float2* eB = reinterpret_cast<const float2*>(eas + (size_t)(i + 1) * 10);
        float2 a0 = __ldg(eA + 0), a1 = __ldg(eA + 1), a2 = __ldg(eA + 2),
               a3 = __ldg(eA + 3), a4 = __ldg(eA + 4);
        float2 b0 = __ldg(eB + 0), b1 = __ldg(eB + 1), b2 = __ldg(eB + 2),
               b3 = __ldg(eB + 3), b4 = __ldg(eB + 4);

        unsigned long long efA[P], efB[P];
#pragma unroll
        for (int j = 0; j < P; j++) { efA[j] = efInit[j]; efB[j] = efInit[j]; }

#pragma unroll
        for (int j = 0; j < P; j++) {
            fma2(efA[j], splat2(a0.x), Wreg[0][j]);
            fma2(efB[j], splat2(b0.x), Wreg[0][j]);
            fma2(efA[j], splat2(a0.y), Wreg[1][j]);
            fma2(efB[j], splat2(b0.y), Wreg[1][j]);
            fma2(efA[j], splat2(a1.x), Wreg[2][j]);
            fma2(efB[j], splat2(b1.x), Wreg[2][j]);
            fma2(efA[j], splat2(a1.y), Wreg[3][j]);
            fma2(efB[j], splat2(b1.y), Wreg[3][j]);
            fma2(efA[j], splat2(a2.x), Wreg[4][j]);
            fma2(efB[j], splat2(b2.x), Wreg[4][j]);
            fma2(efA[j], splat2(a2.y), Wreg[5][j]);
            fma2(efB[j], splat2(b2.y), Wreg[5][j]);
            fma2(efA[j], splat2(a3.x), Wreg[6][j]);
            fma2(efB[j], splat2(b3.x), Wreg[6][j]);
            fma2(efA[j], splat2(a3.y), Wreg[7][j]);
            fma2(efB[j], splat2(b3.y), Wreg[7][j]);
            fma2(efA[j], splat2(a4.x), Wreg[8][j]);
            fma2(efB[j], splat2(b4.x), Wreg[8][j]);
            fma2(efA[j], splat2(a4.y), Wreg[9][j]);
            fma2(efB[j], splat2(b4.y), Wreg[9][j]);
        }

        float zA[V], zB[V];
#pragma unroll
        for (int j = 0; j < P; j++) {
            upk2(zA[2 * j], zA[2 * j + 1], efA[j]);
            upk2(zB[2 * j], zB[2 * j + 1], efB[j]);
        }
        float pA = 0.f, pB = 0.f;
#pragma unroll
        for (int v = 0; v < V; v++) {
            float tA = zA[v] + xA[v];
            tA = tA > 0.f ? tA : 0.2f * tA;
            pA += tA * attv[v];
            float tB = zB[v] + xB[v];
            tB = tB > 0.f ? tB : 0.2f * tB;
            pB += tB * attv[v];
        }
        pA += __shfl_xor_sync(0xffffffffu, pA, 8);
        pB += __shfl_xor_sync(0xffffffffu, pB, 8);
        pA += __shfl_xor_sync(0xffffffffu, pA, 4);
        pB += __shfl_xor_sync(0xffffffffu, pB, 4);
        pA += __shfl_xor_sync(0xffffffffu, pA, 2);
        pB += __shfl_xor_sync(0xffffffffu, pB, 2);
        pA += __shfl_xor_sync(0xffffffffu, pA, 1);
        pB += __shfl_xor_sync(0xffffffffu, pB, 1);
        // each lane now holds its own head's logit
        const float wA = __expf(pA);
        const float wB = __expf(pB);
        s += wA + wB;
#pragma unroll
        for (int v = 0; v < V; v++) acc[v] += wA * xA[v] + wB * xB[v];
    }
    if (i < end) {
        const int sA = srcs[i];
        float xA[V];
        if constexpr (V == 4) {
            float4 t = reinterpret_cast<const float4*>(xl + (size_t)sA * HC)[lane];
            xA[0] = t.x; xA[1] = t.y; xA[2] = t.z; xA[3] = t.w;
        } else {
            float2 t = reinterpret_cast<const float2*>(xl + (size_t)sA * HC)[lane];
            xA[0] = t.x; xA[1] = t.y;
        }
        const float2* eA = reinterpret_cast<const float2*>(eas + (size_t)i * 10);
        float2 a0 = __ldg(eA + 0), a1 = __ldg(eA + 1), a2 = __ldg(eA + 2),
               a3 = __ldg(eA + 3), a4 = __ldg(eA + 4);
        unsigned long long efA[P];
#pragma unroll
        for (int j = 0; j < P; j++) efA[j] = efInit[j];
#pragma unroll
        for (int j = 0; j < P; j++) {
            fma2(efA[j], splat2(a0.x), Wreg[0][j]);
            fma2(efA[j], splat2(a0.y), Wreg[1][j]);
            fma2(efA[j], splat2(a1.x), Wreg[2][j]);
            fma2(efA[j], splat2(a1.y), Wreg[3][j]);
            fma2(efA[j], splat2(a2.x), Wreg[4][j]);
            fma2(efA[j], splat2(a2.y), Wreg[5][j]);
            fma2(efA[j], splat2(a3.x), Wreg[6][j]);
            fma2(efA[j], splat2(a3.y), Wreg[7][j]);
            fma2(efA[j], splat2(a4.x), Wreg[8][j]);
            fma2(efA[j], splat2(a4.y), Wreg[9][j]);
        }
        float zA[V];
#pragma unroll
        for (int j = 0; j < P; j++) upk2(zA[2 * j], zA[2 * j + 1], efA[j]);
        float pA = 0.f;
#pragma unroll
        for (int v = 0; v < V; v++) {
            float tA = zA[v] + xA[v];
            tA = tA > 0.f ? tA : 0.2f * tA;
            pA += tA * attv[v];
        }
        pA += __shfl_xor_sync(0xffffffffu, pA, 8);
        pA += __shfl_xor_sync(0xffffffffu, pA, 4);
        pA += __shfl_xor_sync(0xffffffffu, pA, 2);
        pA += __shfl_xor_sync(0xffffffffu, pA, 1);
        const float wA = __expf(pA);
        s += wA;
#pragma unroll
        for (int v = 0; v < V; v++) acc[v] += wA * xA[v];
    }

    const float inv = 1.f / fmaxf(s, 1e-16f);
    float r[V];
#pragma unroll
    for (int v = 0; v < V; v++) r[v] = acc[v] * inv;

    if constexpr (CONCAT) {
        float2 o;
        o.x = r[0] + bias[c0];
        o.y = r[1] + bias[c0 + 1];
        reinterpret_cast<float2*>(out + (size_t)d * 64)[lane] = o;
    } else {
        float o[V];
#pragma unroll
        for (int v = 0; v < V; v++) {
            float other = __shfl_xor_sync(0xffffffffu, r[v], 16);
            o[v] = 0.5f * (r[v] + other);
        }
        if (lane < 16) {
            float4 w;
            w.x = o[0] + bias[c0];
            w.y = o[1] + bias[c0 + 1];
            w.z = o[2] + bias[c0 + 2];
            w.w = o[3] + bias[c0 + 3];
            reinterpret_cast<float4*>(out + (size_t)d * 64)[lane] = w;
        }
    }
}

// ---------------------------------------------------------------------------
extern "C" void kernel_launch(void* const* d_in, const int* in_sizes, int n_in,
                              void* d_out, int out_size)
{
    const float* x     = (const float*)d_in[0];
    const int*   ei    = (const int*)d_in[1];
    const float* ea    = (const float*)d_in[2];
    const float* Wl0   = (const float*)d_in[3];
    const float* bl0   = (const float*)d_in[4];
    const float* Wr0   = (const float*)d_in[5];
    const float* br0   = (const float*)d_in[6];
    const float* We0   = (const float*)d_in[7];
    const float* att0  = (const float*)d_in[8];
    const float* bias0 = (const float*)d_in[9];
    const float* Wl1   = (const float*)d_in[10];
    const float* bl1   = (const float*)d_in[11];
    const float* Wr1   = (const float*)d_in[12];
    const float* br1   = (const float*)d_in[13];
    const float* We1   = (const float*)d_in[14];
    const float* att1  = (const float*)d_in[15];
    const float* bias1 = (const float*)d_in[16];

    const int n = in_sizes[0] / 79;
    const int E = in_sizes[2] / 10;
    const int* src = ei;
    const int* dst = ei + E;

    void* p;
    cudaGetSymbolAddress(&p, g_xl);     float* xl     = (float*)p;
    cudaGetSymbolAddress(&p, g_xr);     float* xr     = (float*)p;
    cudaGetSymbolAddress(&p, g_h);      float* hbuf   = (float*)p;
    cudaGetSymbolAddress(&p, g_cnt);    int*   cnt    = (int*)p;
    cudaGetSymbolAddress(&p, g_cur);    int*   cur    = (int*)p;
    cudaGetSymbolAddress(&p, g_rowptr); int*   rowptr = (int*)p;
    cudaGetSymbolAddress(&p, g_eids);   int*   eids   = (int*)p;
    cudaGetSymbolAddress(&p, g_srcs);   int*   srcs   = (int*)p;
    cudaGetSymbolAddress(&p, g_eas);    float* eas    = (float*)p;

    cudaFuncSetAttribute(node_gemm<79, 64, false, 4>,
                         cudaFuncAttributeMaxDynamicSharedMemorySize, 79 * 128 * 4);
    cudaFuncSetAttribute(node_gemm<64, 128, true, 4>,
                         cudaFuncAttributeMaxDynamicSharedMemorySize, 64 * 256 * 4);

    const int nB   = (n + 255) / 256;
    const int eB   = (E + 255) / 256;
    const int eaB  = (E * 10 + 255) / 256;
    const int gatB = (n + 7) / 8;                 // warp per node
    const int gB0  = (n + 4 * 8 - 1) / (4 * 8);   // 4 nodes/warp

    // ---- CSR build by dst (shared by all 3 layers) ----
    zero_cnt<<<nB, 256>>>(cnt, n);
    hist_kernel<<<eB, 256>>>(dst, cnt, E);
    scan_kernel<<<1, 1024>>>(cnt, rowptr, cur, n);
    scatter_kernel<<<eB, 256>>>(src, dst, cur, eids, srcs, E);
    permute_ea<<<eaB, 256>>>(ea, eids, eas, E * 10);

    // ---- layer 0 (79 -> 2x32, concat) ----
    node_gemm<79, 64, false, 4><<<gB0, 256, 79 * 128 * 4>>>(
        x, Wl0, bl0, Wr0, br0, xl, xr, n);
    gat_node<64, true><<<gatB, 256>>>(xl, xr, eas, srcs, rowptr,
                                      We0, att0, bias0, hbuf, n);

    // ---- layers 1, 2 (64 -> 2x64, mean) ----
    for (int i = 0; i < 2; i++) {
        node_gemm<64, 128, true, 4><<<gB0, 256, 64 * 256 * 4>>>(
            hbuf, Wl1 + (size_t)i * 64 * 128, bl1 + i * 128,
            Wr1 + (size_t)i * 64 * 128, br1 + i * 128, xl, xr, n);
        float* outp = (i == 1) ? (float*)d_out : hbuf;
        gat_node<128, false><<<gatB, 256>>>(xl, xr, eas, srcs, rowptr,
                                            We1 + (size_t)i * 10 * 128,
                                            att1 + (size_t)i * 128,
                                            bias1 + i * 64, outp, n);
    }
}